// round 2
// baseline (speedup 1.0000x reference)
#include <cuda_runtime.h>
#include <cstdint>

// out = Wlat^T X  +  sigmoid(gate) * softmax(X Wa X^T) X Wb
//   Wa[k][n] = sum_e Wq[e,k] Wk[e,n] / 16
//   Wb[k][n] = sum_e Wo[n,e] Wv[e,k]
// B=8, T=2048, P=13, D=256; 16384 tokens; warp = 1 token (padded to 16 rows).

#define THREADS 256
#define SXR 260       // X smem row stride
#define SP1 72        // phase-1 panel stride (32 x 64)
#define SP2 136       // phase-2 panel stride (32 x 128)
#define P1BUF 2304
#define P2BUF 4352
#define SCB 68        // chunk buffer stride (16 x 64)
#define SAT 20        // attn stride (16 x 16)

#define SM_X 0                 // 8*16*260 = 33280
#define SM_P 33280             // 2*4352 = 8704 (panels, union ph1/ph2)
#define SM_C 41984             // 8*16*68 = 8704
#define SM_A 50688             // 8*16*20 = 2560
#define SM_W 53248             // 320
#define SMEM_FLOATS 53568
#define SMEM_BYTES (SMEM_FLOATS * 4)

__device__ float g_Wa[256 * 256];
__device__ float g_Wb[256 * 256];

__device__ __forceinline__ uint32_t f2tf(float x) {
    uint32_t r;
    asm("cvt.rna.tf32.f32 %0, %1;" : "=r"(r) : "f"(x));
    return r;
}

__device__ __forceinline__ void mma8(float* d,
                                     uint32_t a0, uint32_t a1, uint32_t a2, uint32_t a3,
                                     uint32_t b0, uint32_t b1) {
    asm volatile(
        "mma.sync.aligned.m16n8k8.row.col.f32.tf32.tf32.f32 "
        "{%0,%1,%2,%3},{%4,%5,%6,%7},{%8,%9},{%0,%1,%2,%3};\n"
        : "+f"(d[0]), "+f"(d[1]), "+f"(d[2]), "+f"(d[3])
        : "r"(a0), "r"(a1), "r"(a2), "r"(a3), "r"(b0), "r"(b1));
}

// ------------------------------- setup --------------------------------------
__global__ void lc_setup(const float* __restrict__ Wq, const float* __restrict__ Wk,
                         const float* __restrict__ Wv, const float* __restrict__ Wo) {
    int n = threadIdx.x;
    int k = blockIdx.x;
    if (blockIdx.y == 0) {
        float acc = 0.f;
        for (int e = 0; e < 256; ++e)
            acc += Wq[e * 256 + k] * Wk[e * 256 + n];
        acc *= (1.0f / 16.0f);
        g_Wa[k * 256 + n] = __uint_as_float(f2tf(acc));
    } else {
        float acc = 0.f;
        for (int e = 0; e < 256; ++e)
            acc += Wo[n * 256 + e] * Wv[e * 256 + k];
        g_Wb[k * 256 + n] = __uint_as_float(f2tf(acc));
    }
}

// -------------------------------- main --------------------------------------
__global__ void __launch_bounds__(THREADS, 1)
lc_main(const float* __restrict__ h, const float* __restrict__ Wlat,
        const float* __restrict__ gate, float* __restrict__ out) {
    extern __shared__ float smem[];
    const int tid = threadIdx.x;
    const int w = tid >> 5, lane = tid & 31;
    const int g = lane >> 2, tg = lane & 3;
    const long token = (long)blockIdx.x * 8 + w;

    float* Xs = smem + SM_X + w * 16 * SXR;
    float* Cb = smem + SM_C + w * 16 * SCB;
    float* As = smem + SM_A + w * 16 * SAT;
    float* Wls = smem + SM_W;

    // ---- load X (13x256 fp32), zero pad rows 13..15 ----
    const float* hx = h + token * 3328;
    for (int i = lane; i < 832; i += 32) {
        int row = i >> 6, c4 = (i & 63) << 2;
        *(float4*)(Xs + row * SXR + c4) = *(const float4*)(hx + row * 256 + c4);
    }
    for (int i = lane; i < 768; i += 32) {
        int row = 13 + (i >> 8), c = i & 255;
        Xs[row * SXR + c] = 0.f;
    }
    if (tid < 208) {
        int p = tid >> 4, r = tid & 15;
        Wls[p * 16 + r] = (r < 13) ? Wlat[p * 13 + r] : 0.f;
    }
    float sig;
    { float gv = gate[0]; sig = 1.f / (1.f + __expf(-gv)); }
    __syncthreads();

    // =================== phase 1: Y = X Wa, S = Y X^T ===================
    float s0[4] = {0, 0, 0, 0}, s1[4] = {0, 0, 0, 0};

    for (int nc = 0; nc < 4; ++nc) {
        float ya[8][4];
#pragma unroll
        for (int i = 0; i < 8; ++i)
#pragma unroll
            for (int j = 0; j < 4; ++j) ya[i][j] = 0.f;

        float4 stg[2];
#pragma unroll
        for (int j = 0; j < 2; ++j) {
            int idx = tid + j * 256, row = idx >> 4, c4 = (idx & 15) << 2;
            stg[j] = *(const float4*)(g_Wa + row * 256 + nc * 64 + c4);
        }
#pragma unroll
        for (int j = 0; j < 2; ++j) {
            int idx = tid + j * 256, row = idx >> 4, c4 = (idx & 15) << 2;
            *(float4*)(smem + SM_P + row * SP1 + c4) = stg[j];
        }
        __syncthreads();

        for (int kp = 0; kp < 8; ++kp) {
            if (kp < 7) {
#pragma unroll
                for (int j = 0; j < 2; ++j) {
                    int idx = tid + j * 256, row = idx >> 4, c4 = (idx & 15) << 2;
                    stg[j] = *(const float4*)(g_Wa + ((kp + 1) * 32 + row) * 256 + nc * 64 + c4);
                }
            }
            const float* cur = smem + SM_P + (kp & 1) * P1BUF;
#pragma unroll
            for (int ks = 0; ks < 4; ++ks) {
                int kc = kp * 32 + ks * 8;
                uint32_t a0 = f2tf(Xs[g * SXR + kc + tg]);
                uint32_t a1 = f2tf(Xs[(g + 8) * SXR + kc + tg]);
                uint32_t a2 = f2tf(Xs[g * SXR + kc + tg + 4]);
                uint32_t a3 = f2tf(Xs[(g + 8) * SXR + kc + tg + 4]);
#pragma unroll
                for (int nt = 0; nt < 8; ++nt) {
                    uint32_t b0 = __float_as_uint(cur[(ks * 8 + tg) * SP1 + nt * 8 + g]);
                    uint32_t b1 = __float_as_uint(cur[(ks * 8 + tg + 4) * SP1 + nt * 8 + g]);
                    mma8(ya[nt], a0, a1, a2, a3, b0, b1);
                }
            }
            if (kp < 7) {
                float* nxt = smem + SM_P + ((kp + 1) & 1) * P1BUF;
#pragma unroll
                for (int j = 0; j < 2; ++j) {
                    int idx = tid + j * 256, row = idx >> 4, c4 = (idx & 15) << 2;
                    *(float4*)(nxt + row * SP1 + c4) = stg[j];
                }
            }
            __syncthreads();
        }

        // Ychunk -> Cb (tf32), S += Ychunk * Xchunk^T
        __syncwarp();
#pragma unroll
        for (int nt = 0; nt < 8; ++nt) {
            int c = nt * 8 + 2 * tg;
            Cb[g * SCB + c]           = __uint_as_float(f2tf(ya[nt][0]));
            Cb[g * SCB + c + 1]       = __uint_as_float(f2tf(ya[nt][1]));
            Cb[(g + 8) * SCB + c]     = __uint_as_float(f2tf(ya[nt][2]));
            Cb[(g + 8) * SCB + c + 1] = __uint_as_float(f2tf(ya[nt][3]));
        }
        __syncwarp();
#pragma unroll
        for (int ks = 0; ks < 8; ++ks) {
            uint32_t a0 = __float_as_uint(Cb[g * SCB + ks * 8 + tg]);
            uint32_t a1 = __float_as_uint(Cb[(g + 8) * SCB + ks * 8 + tg]);
            uint32_t a2 = __float_as_uint(Cb[g * SCB + ks * 8 + tg + 4]);
            uint32_t a3 = __float_as_uint(Cb[(g + 8) * SCB + ks * 8 + tg + 4]);
            int xc = nc * 64 + ks * 8;
            uint32_t b0 = f2tf(Xs[g * SXR + xc + tg]);
            uint32_t b1 = f2tf(Xs[g * SXR + xc + tg + 4]);
            mma8(s0, a0, a1, a2, a3, b0, b1);
            uint32_t c0 = f2tf(Xs[(g + 8) * SXR + xc + tg]);
            uint32_t c1 = f2tf(Xs[(g + 8) * SXR + xc + tg + 4]);
            mma8(s1, a0, a1, a2, a3, c0, c1);
        }
        __syncwarp();
    }

    // =================== softmax over cols 0..12 ===================
    {
        // element cols: s*[0]: 2tg, s*[1]: 2tg+1 (tile0) / +8 (tile1)
        int c0 = 2 * tg, c1 = 2 * tg + 1, c2 = 8 + 2 * tg, c3 = 9 + 2 * tg;
        bool v0 = c0 < 13, v1 = c1 < 13, v2 = c2 < 13, v3 = c3 < 13;
        const float NEG = -1e30f;
        float m0 = fmaxf(fmaxf(v0 ? s0[0] : NEG, v1 ? s0[1] : NEG),
                         fmaxf(v2 ? s1[0] : NEG, v3 ? s1[1] : NEG));
        float m1 = fmaxf(fmaxf(v0 ? s0[2] : NEG, v1 ? s0[3] : NEG),
                         fmaxf(v2 ? s1[2] : NEG, v3 ? s1[3] : NEG));
        m0 = fmaxf(m0, __shfl_xor_sync(0xffffffffu, m0, 1));
        m0 = fmaxf(m0, __shfl_xor_sync(0xffffffffu, m0, 2));
        m1 = fmaxf(m1, __shfl_xor_sync(0xffffffffu, m1, 1));
        m1 = fmaxf(m1, __shfl_xor_sync(0xffffffffu, m1, 2));
        float e00 = v0 ? __expf(s0[0] - m0) : 0.f;
        float e01 = v1 ? __expf(s0[1] - m0) : 0.f;
        float e02 = v2 ? __expf(s1[0] - m0) : 0.f;
        float e03 = v3 ? __expf(s1[1] - m0) : 0.f;
        float e10 = v0 ? __expf(s0[2] - m1) : 0.f;
        float e11 = v1 ? __expf(s0[3] - m1) : 0.f;
        float e12 = v2 ? __expf(s1[2] - m1) : 0.f;
        float e13 = v3 ? __expf(s1[3] - m1) : 0.f;
        float d0 = e00 + e01 + e02 + e03;
        float d1 = e10 + e11 + e12 + e13;
        d0 += __shfl_xor_sync(0xffffffffu, d0, 1);
        d0 += __shfl_xor_sync(0xffffffffu, d0, 2);
        d1 += __shfl_xor_sync(0xffffffffu, d1, 1);
        d1 += __shfl_xor_sync(0xffffffffu, d1, 2);
        float r0 = 1.f / d0, r1 = 1.f / d1;
        As[g * SAT + c0]       = __uint_as_float(f2tf(e00 * r0));
        As[g * SAT + c1]       = __uint_as_float(f2tf(e01 * r0));
        As[g * SAT + c2]       = __uint_as_float(f2tf(e02 * r0));
        As[g * SAT + c3]       = __uint_as_float(f2tf(e03 * r0));
        As[(g + 8) * SAT + c0] = __uint_as_float(f2tf(e10 * r1));
        As[(g + 8) * SAT + c1] = __uint_as_float(f2tf(e11 * r1));
        As[(g + 8) * SAT + c2] = __uint_as_float(f2tf(e12 * r1));
        As[(g + 8) * SAT + c3] = __uint_as_float(f2tf(e13 * r1));
        __syncwarp();
    }

    // =========== phase 2: Z = A X (chunked), R = Z Wb, epilogue ===========
    for (int nh = 0; nh < 2; ++nh) {
        float ra[16][4];
#pragma unroll
        for (int i = 0; i < 16; ++i)
#pragma unroll
            for (int j = 0; j < 4; ++j) ra[i][j] = 0.f;

        float4 stg2[4];
#pragma unroll
        for (int j = 0; j < 4; ++j) {
            int idx = tid + j * 256, row = idx >> 5, c4 = (idx & 31) << 2;
            stg2[j] = *(const float4*)(g_Wb + row * 256 + nh * 128 + c4);
        }
#pragma unroll
        for (int j = 0; j < 4; ++j) {
            int idx = tid + j * 256, row = idx >> 5, c4 = (idx & 31) << 2;
            *(float4*)(smem + SM_P + row * SP2 + c4) = stg2[j];
        }
        __syncthreads();

        int ip = 0;
        for (int dc = 0; dc < 4; ++dc) {
            // Zchunk = attn * X[:, dc*64 .. +64)
            float za[8][4];
#pragma unroll
            for (int i = 0; i < 8; ++i)
#pragma unroll
                for (int j = 0; j < 4; ++j) za[i][j] = 0.f;
#pragma unroll
            for (int ks = 0; ks < 2; ++ks) {
                uint32_t a0 = __float_as_uint(As[g * SAT + ks * 8 + tg]);
                uint32_t a1 = __float_as_uint(As[(g + 8) * SAT + ks * 8 + tg]);
                uint32_t a2 = __float_as_uint(As[g * SAT + ks * 8 + tg + 4]);
                uint32_t a3 = __float_as_uint(As[(g + 8) * SAT + ks * 8 + tg + 4]);
#pragma unroll
                for (int nt = 0; nt < 8; ++nt) {
                    int xc = dc * 64 + nt * 8 + g;
                    uint32_t b0 = f2tf(Xs[(ks * 8 + tg) * SXR + xc]);
                    uint32_t b1 = f2tf(Xs[(ks * 8 + tg + 4) * SXR + xc]);
                    mma8(za[nt], a0, a1, a2, a3, b0, b1);
                }
            }
            __syncwarp();
#pragma unroll
            for (int nt = 0; nt < 8; ++nt) {
                int c = nt * 8 + 2 * tg;
                Cb[g * SCB + c]           = __uint_as_float(f2tf(za[nt][0]));
                Cb[g * SCB + c + 1]       = __uint_as_float(f2tf(za[nt][1]));
                Cb[(g + 8) * SCB + c]     = __uint_as_float(f2tf(za[nt][2]));
                Cb[(g + 8) * SCB + c + 1] = __uint_as_float(f2tf(za[nt][3]));
            }
            __syncwarp();

            for (int kp2 = 0; kp2 < 2; ++kp2, ++ip) {
                if (ip < 7) {
                    int nip = ip + 1, ndc = nip >> 1, nkp = nip & 1;
#pragma unroll
                    for (int j = 0; j < 4; ++j) {
                        int idx = tid + j * 256, row = idx >> 5, c4 = (idx & 31) << 2;
                        stg2[j] = *(const float4*)(g_Wb + (ndc * 64 + nkp * 32 + row) * 256 +
                                                   nh * 128 + c4);
                    }
                }
                const float* cur = smem + SM_P + (ip & 1) * P2BUF;
#pragma unroll
                for (int ks = 0; ks < 4; ++ks) {
                    int kc = kp2 * 32 + ks * 8;
                    uint32_t a0 = __float_as_uint(Cb[g * SCB + kc + tg]);
                    uint32_t a1 = __float_as_uint(Cb[(g + 8) * SCB + kc + tg]);
                    uint32_t a2 = __float_as_uint(Cb[g * SCB + kc + tg + 4]);
                    uint32_t a3 = __float_as_uint(Cb[(g + 8) * SCB + kc + tg + 4]);
#pragma unroll
                    for (int nt = 0; nt < 16; ++nt) {
                        uint32_t b0 = __float_as_uint(cur[(ks * 8 + tg) * SP2 + nt * 8 + g]);
                        uint32_t b1 = __float_as_uint(cur[(ks * 8 + tg + 4) * SP2 + nt * 8 + g]);
                        mma8(ra[nt], a0, a1, a2, a3, b0, b1);
                    }
                }
                if (ip < 7) {
                    float* nxt = smem + SM_P + ((ip + 1) & 1) * P2BUF;
#pragma unroll
                    for (int j = 0; j < 4; ++j) {
                        int idx = tid + j * 256, row = idx >> 5, c4 = (idx & 31) << 2;
                        *(float4*)(nxt + row * SP2 + c4) = stg2[j];
                    }
                }
                __syncthreads();
            }
        }

        // ---- epilogue: exact fp32 residual + sig * R ----
        long obase = token * 3328;
#pragma unroll
        for (int nt = 0; nt < 16; ++nt) {
            int c = nh * 128 + nt * 8 + 2 * tg;
            float r00 = 0.f, r01 = 0.f, r10 = 0.f, r11 = 0.f;
#pragma unroll
            for (int p = 0; p < 13; ++p) {
                float wg = Wls[p * 16 + g];
                float wg8 = Wls[p * 16 + g + 8];
                float2 x = *(float2*)(Xs + p * SXR + c);
                r00 += wg * x.x;  r01 += wg * x.y;
                r10 += wg8 * x.x; r11 += wg8 * x.y;
            }
            float2 o0 = make_float2(r00 + sig * ra[nt][0], r01 + sig * ra[nt][1]);
            *(float2*)(out + obase + g * 256 + c) = o0;
            if (g < 5) {
                float2 o1 = make_float2(r10 + sig * ra[nt][2], r11 + sig * ra[nt][3]);
                *(float2*)(out + obase + (g + 8) * 256 + c) = o1;
            }
        }
    }
}

// ------------------------------ launch --------------------------------------
extern "C" void kernel_launch(void* const* d_in, const int* in_sizes, int n_in,
                              void* d_out, int out_size) {
    const float* h    = (const float*)d_in[0];
    const float* Wq   = (const float*)d_in[1];
    const float* Wk   = (const float*)d_in[2];
    const float* Wv   = (const float*)d_in[3];
    const float* Wo   = (const float*)d_in[4];
    const float* Wlat = (const float*)d_in[5];
    const float* gate = (const float*)d_in[6];
    float* out = (float*)d_out;

    static bool attr_done = false;
    if (!attr_done) {
        cudaFuncSetAttribute(lc_main, cudaFuncAttributeMaxDynamicSharedMemorySize, SMEM_BYTES);
        attr_done = true;
    }

    lc_setup<<<dim3(256, 2), 256>>>(Wq, Wk, Wv, Wo);
    lc_main<<<2048, THREADS, SMEM_BYTES>>>(h, Wlat, gate, out);
}

// round 3
// speedup vs baseline: 1.0013x; 1.0013x over previous
#include <cuda_runtime.h>
#include <cstdint>

// out = Wlat^T X  +  sigmoid(gate) * softmax(X Wa X^T) X Wb
//   Wa[k][n] = sum_e Wq[e,k] Wk[e,n] / 16
//   Wb[k][n] = sum_e Wo[n,e] Wv[e,k]
// B=8, T=2048, P=13, D=256; 16384 tokens; warp = 1 token (padded to 16 rows).

#define THREADS 256
#define SXR 260       // X smem row stride
#define SP1 72        // phase-1 panel stride (32 x 64)
#define SP2 136       // phase-2 panel stride (32 x 128)
#define P1BUF 2304
#define P2BUF 4352
#define SCB 68        // chunk buffer stride (16 x 64)
#define SAT 20        // attn stride (16 x 16)

#define SM_X 0                 // 8*16*260 = 33280
#define SM_P 33280             // 2*4352 = 8704 (panels, union ph1/ph2)
#define SM_C 41984             // 8*16*68 = 8704
#define SM_A 50688             // 8*16*20 = 2560
#define SM_W 53248             // 320
#define SMEM_FLOATS 53568
#define SMEM_BYTES (SMEM_FLOATS * 4)

__device__ float g_Wa[256 * 256];
__device__ float g_Wb[256 * 256];

__device__ __forceinline__ uint32_t f2tf(float x) {
    uint32_t r;
    asm("cvt.rna.tf32.f32 %0, %1;" : "=r"(r) : "f"(x));
    return r;
}

__device__ __forceinline__ void mma8(float* d,
                                     uint32_t a0, uint32_t a1, uint32_t a2, uint32_t a3,
                                     uint32_t b0, uint32_t b1) {
    asm volatile(
        "mma.sync.aligned.m16n8k8.row.col.f32.tf32.tf32.f32 "
        "{%0,%1,%2,%3},{%4,%5,%6,%7},{%8,%9},{%0,%1,%2,%3};\n"
        : "+f"(d[0]), "+f"(d[1]), "+f"(d[2]), "+f"(d[3])
        : "r"(a0), "r"(a1), "r"(a2), "r"(a3), "r"(b0), "r"(b1));
}

// ------------------------------- setup --------------------------------------
__global__ void lc_setup(const float* __restrict__ Wq, const float* __restrict__ Wk,
                         const float* __restrict__ Wv, const float* __restrict__ Wo) {
    int n = threadIdx.x;
    int k = blockIdx.x;
    if (blockIdx.y == 0) {
        float acc = 0.f;
        for (int e = 0; e < 256; ++e)
            acc += Wq[e * 256 + k] * Wk[e * 256 + n];
        acc *= (1.0f / 16.0f);
        g_Wa[k * 256 + n] = __uint_as_float(f2tf(acc));
    } else {
        float acc = 0.f;
        for (int e = 0; e < 256; ++e)
            acc += Wo[n * 256 + e] * Wv[e * 256 + k];
        g_Wb[k * 256 + n] = __uint_as_float(f2tf(acc));
    }
}

// -------------------------------- main --------------------------------------
__global__ void __launch_bounds__(THREADS, 1)
lc_main(const float* __restrict__ h, const float* __restrict__ Wlat,
        const float* __restrict__ gate, float* __restrict__ out) {
    extern __shared__ float smem[];
    const int tid = threadIdx.x;
    const int w = tid >> 5, lane = tid & 31;
    const int g = lane >> 2, tg = lane & 3;
    const long token = (long)blockIdx.x * 8 + w;

    float* Xs = smem + SM_X + w * 16 * SXR;
    float* Cb = smem + SM_C + w * 16 * SCB;
    float* As = smem + SM_A + w * 16 * SAT;
    float* Wls = smem + SM_W;

    // ---- load X (13x256 fp32), zero pad rows 13..15 ----
    const float* hx = h + token * 3328;
    for (int i = lane; i < 832; i += 32) {
        int row = i >> 6, c4 = (i & 63) << 2;
        *(float4*)(Xs + row * SXR + c4) = *(const float4*)(hx + row * 256 + c4);
    }
    for (int i = lane; i < 768; i += 32) {
        int row = 13 + (i >> 8), c = i & 255;
        Xs[row * SXR + c] = 0.f;
    }
    if (tid < 208) {
        int p = tid >> 4, r = tid & 15;
        Wls[p * 16 + r] = (r < 13) ? Wlat[p * 13 + r] : 0.f;
    }
    float sig;
    { float gv = gate[0]; sig = 1.f / (1.f + __expf(-gv)); }
    __syncthreads();

    // =================== phase 1: Y = X Wa, S = Y X^T ===================
    float s0[4] = {0, 0, 0, 0}, s1[4] = {0, 0, 0, 0};

    for (int nc = 0; nc < 4; ++nc) {
        float ya[8][4];
#pragma unroll
        for (int i = 0; i < 8; ++i)
#pragma unroll
            for (int j = 0; j < 4; ++j) ya[i][j] = 0.f;

        float4 stg[2];
#pragma unroll
        for (int j = 0; j < 2; ++j) {
            int idx = tid + j * 256, row = idx >> 4, c4 = (idx & 15) << 2;
            stg[j] = *(const float4*)(g_Wa + row * 256 + nc * 64 + c4);
        }
#pragma unroll
        for (int j = 0; j < 2; ++j) {
            int idx = tid + j * 256, row = idx >> 4, c4 = (idx & 15) << 2;
            *(float4*)(smem + SM_P + row * SP1 + c4) = stg[j];
        }
        __syncthreads();

        for (int kp = 0; kp < 8; ++kp) {
            if (kp < 7) {
#pragma unroll
                for (int j = 0; j < 2; ++j) {
                    int idx = tid + j * 256, row = idx >> 4, c4 = (idx & 15) << 2;
                    stg[j] = *(const float4*)(g_Wa + ((kp + 1) * 32 + row) * 256 + nc * 64 + c4);
                }
            }
            const float* cur = smem + SM_P + (kp & 1) * P1BUF;
#pragma unroll
            for (int ks = 0; ks < 4; ++ks) {
                int kc = kp * 32 + ks * 8;
                uint32_t a0 = f2tf(Xs[g * SXR + kc + tg]);
                uint32_t a1 = f2tf(Xs[(g + 8) * SXR + kc + tg]);
                uint32_t a2 = f2tf(Xs[g * SXR + kc + tg + 4]);
                uint32_t a3 = f2tf(Xs[(g + 8) * SXR + kc + tg + 4]);
#pragma unroll
                for (int nt = 0; nt < 8; ++nt) {
                    uint32_t b0 = __float_as_uint(cur[(ks * 8 + tg) * SP1 + nt * 8 + g]);
                    uint32_t b1 = __float_as_uint(cur[(ks * 8 + tg + 4) * SP1 + nt * 8 + g]);
                    mma8(ya[nt], a0, a1, a2, a3, b0, b1);
                }
            }
            if (kp < 7) {
                float* nxt = smem + SM_P + ((kp + 1) & 1) * P1BUF;
#pragma unroll
                for (int j = 0; j < 2; ++j) {
                    int idx = tid + j * 256, row = idx >> 4, c4 = (idx & 15) << 2;
                    *(float4*)(nxt + row * SP1 + c4) = stg[j];
                }
            }
            __syncthreads();
        }

        // Ychunk -> Cb (tf32), S += Ychunk * Xchunk^T
        __syncwarp();
#pragma unroll
        for (int nt = 0; nt < 8; ++nt) {
            int c = nt * 8 + 2 * tg;
            Cb[g * SCB + c]           = __uint_as_float(f2tf(ya[nt][0]));
            Cb[g * SCB + c + 1]       = __uint_as_float(f2tf(ya[nt][1]));
            Cb[(g + 8) * SCB + c]     = __uint_as_float(f2tf(ya[nt][2]));
            Cb[(g + 8) * SCB + c + 1] = __uint_as_float(f2tf(ya[nt][3]));
        }
        __syncwarp();
#pragma unroll
        for (int ks = 0; ks < 8; ++ks) {
            uint32_t a0 = __float_as_uint(Cb[g * SCB + ks * 8 + tg]);
            uint32_t a1 = __float_as_uint(Cb[(g + 8) * SCB + ks * 8 + tg]);
            uint32_t a2 = __float_as_uint(Cb[g * SCB + ks * 8 + tg + 4]);
            uint32_t a3 = __float_as_uint(Cb[(g + 8) * SCB + ks * 8 + tg + 4]);
            int xc = nc * 64 + ks * 8;
            uint32_t b0 = f2tf(Xs[g * SXR + xc + tg]);
            uint32_t b1 = f2tf(Xs[g * SXR + xc + tg + 4]);
            mma8(s0, a0, a1, a2, a3, b0, b1);
            uint32_t c0 = f2tf(Xs[(g + 8) * SXR + xc + tg]);
            uint32_t c1 = f2tf(Xs[(g + 8) * SXR + xc + tg + 4]);
            mma8(s1, a0, a1, a2, a3, c0, c1);
        }
        __syncwarp();
    }

    // =================== softmax over cols 0..12 ===================
    {
        // element cols: s*[0]: 2tg, s*[1]: 2tg+1 (tile0) / +8 (tile1)
        int c0 = 2 * tg, c1 = 2 * tg + 1, c2 = 8 + 2 * tg, c3 = 9 + 2 * tg;
        bool v0 = c0 < 13, v1 = c1 < 13, v2 = c2 < 13, v3 = c3 < 13;
        const float NEG = -1e30f;
        float m0 = fmaxf(fmaxf(v0 ? s0[0] : NEG, v1 ? s0[1] : NEG),
                         fmaxf(v2 ? s1[0] : NEG, v3 ? s1[1] : NEG));
        float m1 = fmaxf(fmaxf(v0 ? s0[2] : NEG, v1 ? s0[3] : NEG),
                         fmaxf(v2 ? s1[2] : NEG, v3 ? s1[3] : NEG));
        m0 = fmaxf(m0, __shfl_xor_sync(0xffffffffu, m0, 1));
        m0 = fmaxf(m0, __shfl_xor_sync(0xffffffffu, m0, 2));
        m1 = fmaxf(m1, __shfl_xor_sync(0xffffffffu, m1, 1));
        m1 = fmaxf(m1, __shfl_xor_sync(0xffffffffu, m1, 2));
        float e00 = v0 ? __expf(s0[0] - m0) : 0.f;
        float e01 = v1 ? __expf(s0[1] - m0) : 0.f;
        float e02 = v2 ? __expf(s1[0] - m0) : 0.f;
        float e03 = v3 ? __expf(s1[1] - m0) : 0.f;
        float e10 = v0 ? __expf(s0[2] - m1) : 0.f;
        float e11 = v1 ? __expf(s0[3] - m1) : 0.f;
        float e12 = v2 ? __expf(s1[2] - m1) : 0.f;
        float e13 = v3 ? __expf(s1[3] - m1) : 0.f;
        float d0 = e00 + e01 + e02 + e03;
        float d1 = e10 + e11 + e12 + e13;
        d0 += __shfl_xor_sync(0xffffffffu, d0, 1);
        d0 += __shfl_xor_sync(0xffffffffu, d0, 2);
        d1 += __shfl_xor_sync(0xffffffffu, d1, 1);
        d1 += __shfl_xor_sync(0xffffffffu, d1, 2);
        float r0 = 1.f / d0, r1 = 1.f / d1;
        As[g * SAT + c0]       = __uint_as_float(f2tf(e00 * r0));
        As[g * SAT + c1]       = __uint_as_float(f2tf(e01 * r0));
        As[g * SAT + c2]       = __uint_as_float(f2tf(e02 * r0));
        As[g * SAT + c3]       = __uint_as_float(f2tf(e03 * r0));
        As[(g + 8) * SAT + c0] = __uint_as_float(f2tf(e10 * r1));
        As[(g + 8) * SAT + c1] = __uint_as_float(f2tf(e11 * r1));
        As[(g + 8) * SAT + c2] = __uint_as_float(f2tf(e12 * r1));
        As[(g + 8) * SAT + c3] = __uint_as_float(f2tf(e13 * r1));
        __syncwarp();
    }

    // =========== phase 2: Z = A X (chunked), R = Z Wb, epilogue ===========
    for (int nh = 0; nh < 2; ++nh) {
        float ra[16][4];
#pragma unroll
        for (int i = 0; i < 16; ++i)
#pragma unroll
            for (int j = 0; j < 4; ++j) ra[i][j] = 0.f;

        float4 stg2[4];
#pragma unroll
        for (int j = 0; j < 4; ++j) {
            int idx = tid + j * 256, row = idx >> 5, c4 = (idx & 31) << 2;
            stg2[j] = *(const float4*)(g_Wb + row * 256 + nh * 128 + c4);
        }
#pragma unroll
        for (int j = 0; j < 4; ++j) {
            int idx = tid + j * 256, row = idx >> 5, c4 = (idx & 31) << 2;
            *(float4*)(smem + SM_P + row * SP2 + c4) = stg2[j];
        }
        __syncthreads();

        int ip = 0;
        for (int dc = 0; dc < 4; ++dc) {
            // Zchunk = attn * X[:, dc*64 .. +64)
            float za[8][4];
#pragma unroll
            for (int i = 0; i < 8; ++i)
#pragma unroll
                for (int j = 0; j < 4; ++j) za[i][j] = 0.f;
#pragma unroll
            for (int ks = 0; ks < 2; ++ks) {
                uint32_t a0 = __float_as_uint(As[g * SAT + ks * 8 + tg]);
                uint32_t a1 = __float_as_uint(As[(g + 8) * SAT + ks * 8 + tg]);
                uint32_t a2 = __float_as_uint(As[g * SAT + ks * 8 + tg + 4]);
                uint32_t a3 = __float_as_uint(As[(g + 8) * SAT + ks * 8 + tg + 4]);
#pragma unroll
                for (int nt = 0; nt < 8; ++nt) {
                    int xc = dc * 64 + nt * 8 + g;
                    uint32_t b0 = f2tf(Xs[(ks * 8 + tg) * SXR + xc]);
                    uint32_t b1 = f2tf(Xs[(ks * 8 + tg + 4) * SXR + xc]);
                    mma8(za[nt], a0, a1, a2, a3, b0, b1);
                }
            }
            __syncwarp();
#pragma unroll
            for (int nt = 0; nt < 8; ++nt) {
                int c = nt * 8 + 2 * tg;
                Cb[g * SCB + c]           = __uint_as_float(f2tf(za[nt][0]));
                Cb[g * SCB + c + 1]       = __uint_as_float(f2tf(za[nt][1]));
                Cb[(g + 8) * SCB + c]     = __uint_as_float(f2tf(za[nt][2]));
                Cb[(g + 8) * SCB + c + 1] = __uint_as_float(f2tf(za[nt][3]));
            }
            __syncwarp();

            for (int kp2 = 0; kp2 < 2; ++kp2, ++ip) {
                if (ip < 7) {
                    int nip = ip + 1, ndc = nip >> 1, nkp = nip & 1;
#pragma unroll
                    for (int j = 0; j < 4; ++j) {
                        int idx = tid + j * 256, row = idx >> 5, c4 = (idx & 31) << 2;
                        stg2[j] = *(const float4*)(g_Wb + (ndc * 64 + nkp * 32 + row) * 256 +
                                                   nh * 128 + c4);
                    }
                }
                const float* cur = smem + SM_P + (ip & 1) * P2BUF;
#pragma unroll
                for (int ks = 0; ks < 4; ++ks) {
                    int kc = kp2 * 32 + ks * 8;
                    uint32_t a0 = __float_as_uint(Cb[g * SCB + kc + tg]);
                    uint32_t a1 = __float_as_uint(Cb[(g + 8) * SCB + kc + tg]);
                    uint32_t a2 = __float_as_uint(Cb[g * SCB + kc + tg + 4]);
                    uint32_t a3 = __float_as_uint(Cb[(g + 8) * SCB + kc + tg + 4]);
#pragma unroll
                    for (int nt = 0; nt < 16; ++nt) {
                        uint32_t b0 = __float_as_uint(cur[(ks * 8 + tg) * SP2 + nt * 8 + g]);
                        uint32_t b1 = __float_as_uint(cur[(ks * 8 + tg + 4) * SP2 + nt * 8 + g]);
                        mma8(ra[nt], a0, a1, a2, a3, b0, b1);
                    }
                }
                if (ip < 7) {
                    float* nxt = smem + SM_P + ((ip + 1) & 1) * P2BUF;
#pragma unroll
                    for (int j = 0; j < 4; ++j) {
                        int idx = tid + j * 256, row = idx >> 5, c4 = (idx & 31) << 2;
                        *(float4*)(nxt + row * SP2 + c4) = stg2[j];
                    }
                }
                __syncthreads();
            }
        }

        // ---- epilogue: exact fp32 residual + sig * R ----
        long obase = token * 3328;
#pragma unroll
        for (int nt = 0; nt < 16; ++nt) {
            int c = nh * 128 + nt * 8 + 2 * tg;
            float r00 = 0.f, r01 = 0.f, r10 = 0.f, r11 = 0.f;
#pragma unroll
            for (int p = 0; p < 13; ++p) {
                float wg = Wls[p * 16 + g];
                float wg8 = Wls[p * 16 + g + 8];
                float2 x = *(float2*)(Xs + p * SXR + c);
                r00 += wg * x.x;  r01 += wg * x.y;
                r10 += wg8 * x.x; r11 += wg8 * x.y;
            }
            float2 o0 = make_float2(r00 + sig * ra[nt][0], r01 + sig * ra[nt][1]);
            *(float2*)(out + obase + g * 256 + c) = o0;
            if (g < 5) {
                float2 o1 = make_float2(r10 + sig * ra[nt][2], r11 + sig * ra[nt][3]);
                *(float2*)(out + obase + (g + 8) * 256 + c) = o1;
            }
        }
    }
}

// ------------------------------ launch --------------------------------------
extern "C" void kernel_launch(void* const* d_in, const int* in_sizes, int n_in,
                              void* d_out, int out_size) {
    const float* h    = (const float*)d_in[0];
    const float* Wq   = (const float*)d_in[1];
    const float* Wk   = (const float*)d_in[2];
    const float* Wv   = (const float*)d_in[3];
    const float* Wo   = (const float*)d_in[4];
    const float* Wlat = (const float*)d_in[5];
    const float* gate = (const float*)d_in[6];
    float* out = (float*)d_out;

    static bool attr_done = false;
    if (!attr_done) {
        cudaFuncSetAttribute(lc_main, cudaFuncAttributeMaxDynamicSharedMemorySize, SMEM_BYTES);
        attr_done = true;
    }

    lc_setup<<<dim3(256, 2), 256>>>(Wq, Wk, Wv, Wo);
    lc_main<<<2048, THREADS, SMEM_BYTES>>>(h, Wlat, gate, out);
}